// round 13
// baseline (speedup 1.0000x reference)
#include <cuda_runtime.h>
#include <math.h>
#include <stddef.h>
#include <stdint.h>

typedef unsigned long long ull;

// Problem constants
#define BSZ 64
#define TT  3000
#define II  8
#define HH  128
#define GG  512      // 4*H

// ---------------------------------------------------------------------------
// Scratch (device globals; no allocation anywhere)
// ---------------------------------------------------------------------------
__device__ float g_h0 [(size_t)BSZ * TT * HH];   // layer-0 hidden states
__device__ float g_xp1[(size_t)BSZ * TT * GG];   // layer-1 input projection (+biases)
__device__ float g_h1 [(size_t)BSZ * TT * HH];   // layer-1 hidden states
__device__ float g_y  [(size_t)BSZ * TT];        // MLP scalar output per (b,t)

__device__ __forceinline__ float sigf(float x) { return 1.0f / (1.0f + expf(-x)); }

// Packed fp32x2 FMA (sm_100+; ptxas never auto-fuses this)
__device__ __forceinline__ void fma2(ull& d, ull a, ull b) {
    asm("fma.rn.f32x2 %0, %1, %2, %0;" : "+l"(d) : "l"(a), "l"(b));
}
__device__ __forceinline__ ull pack2(float lo, float hi) {
    ull r; asm("mov.b64 %0, {%1, %2};" : "=l"(r) : "f"(lo), "f"(hi)); return r;
}
__device__ __forceinline__ float hsum2(ull v) {
    float lo, hi; asm("mov.b64 {%0, %1}, %2;" : "=f"(lo), "=f"(hi) : "l"(v));
    return lo + hi;
}

// ---- cluster / mbarrier primitives -----------------------------------------
__device__ __forceinline__ unsigned smem_u32(const void* p) {
    return (unsigned)__cvta_generic_to_shared(p);
}
__device__ __forceinline__ unsigned mapa_peer(unsigned laddr, unsigned peer_rank) {
    unsigned r;
    asm("mapa.shared::cluster.u32 %0, %1, %2;" : "=r"(r) : "r"(laddr), "r"(peer_rank));
    return r;
}
__device__ __forceinline__ void sts_cluster_f32(unsigned addr, float v) {
    asm volatile("st.shared::cluster.f32 [%0], %1;" :: "r"(addr), "f"(v) : "memory");
}
__device__ __forceinline__ void mbar_init(unsigned bar, unsigned count) {
    asm volatile("mbarrier.init.shared.b64 [%0], %1;" :: "r"(bar), "r"(count) : "memory");
}
__device__ __forceinline__ void mbar_arrive_cluster(unsigned bar_cluster_addr) {
    asm volatile("mbarrier.arrive.release.cluster.shared::cluster.b64 _, [%0];"
                 :: "r"(bar_cluster_addr) : "memory");
}
__device__ __forceinline__ void mbar_wait_cluster(unsigned bar, unsigned parity) {
    asm volatile(
        "{\n\t.reg .pred P;\n\t"
        "LW%=:\n\t"
        "mbarrier.try_wait.parity.acquire.cluster.shared::cta.b64 P, [%0], %1, 0x989680;\n\t"
        "@!P bra LW%=;\n\t}"
        :: "r"(bar), "r"(parity) : "memory");
}

// ---------------------------------------------------------------------------
// Fused LSTM recurrence, 2-CTA cluster per batch element.
// CTA rank r owns h rows j in [64r, 64r+64). 256 threads:
//   q = tid/64 selects gate type (0=i, 1=f, 2=g, 3=o); jl = tid%64 the h row.
// Each thread owns ONE full gate row (128 weights) in 64 b64 registers.
// h (128 floats) is double-buffered in smem; each CTA's 64 new h values are
// pushed to the peer via st.shared::cluster + per-thread release-arrive on the
// peer's mbarrier (count=64), AFTER the local __syncthreads so peer writes can
// never race this CTA's dot-product reads of the same buffer.
// ---------------------------------------------------------------------------
template<int LAYER>
__global__ __launch_bounds__(256, 1) __cluster_dims__(2, 1, 1)
void lstm_kernel(
    const float* __restrict__ xin,     // LAYER0: x [B,T,8]; LAYER1: unused
    const float* __restrict__ w_ih,    // LAYER0: [512,8];   LAYER1: unused
    const float* __restrict__ w_hh,    // [512,128]
    const float* __restrict__ b_ih,    // LAYER0 only
    const float* __restrict__ b_hh)    // LAYER0 only
{
    __shared__ __align__(16) float hbuf[2][HH];
    __shared__ float fact[64], gact[64], oact[64];
    __shared__ __align__(8) ull mbar[1];

    const int tid  = threadIdx.x;
    const int cta  = blockIdx.x;
    const int b    = cta >> 1;
    const unsigned rank = (unsigned)(cta & 1);
    const int q    = tid >> 6;          // gate type
    const int jl   = tid & 63;          // local h index
    const int j    = (int)rank * 64 + jl;
    const int grow = q * HH + j;        // gate row in [0, 512)

    const float* xsrc = (LAYER == 0) ? xin : g_xp1;
    float*       hout = (LAYER == 0) ? g_h0 : g_h1;

    // --- full gate row of recurrent weights in registers (64 b64 pairs) ---
    ull wr[HH / 2];
    {
        const ull* wp = (const ull*)(w_hh + (size_t)grow * HH);
#pragma unroll
        for (int k = 0; k < HH / 2; k++) wr[k] = wp[k];
    }

    float bsum = 0.f;
    float wi[II];
    if (LAYER == 0) {
#pragma unroll
        for (int k = 0; k < II; k++) wi[k] = w_ih[grow * II + k];
        bsum = b_ih[grow] + b_hh[grow];
    }

    // --- init: zero h, init mbarrier, cluster-wide ordering ---
    if (tid < HH) hbuf[0][tid] = 0.f;
    if (tid == 0) mbar_init(smem_u32(mbar), 64);
    __syncthreads();
    asm volatile("barrier.cluster.arrive.aligned;" ::: "memory");
    asm volatile("barrier.cluster.wait.aligned;"   ::: "memory");

    const unsigned peer       = rank ^ 1u;
    const unsigned peer_hbase = mapa_peer(smem_u32(&hbuf[0][0]), peer);
    const unsigned peer_mbar  = mapa_peer(smem_u32(mbar), peer);
    const unsigned my_mbar    = smem_u32(mbar);

    float c = 0.f;
    int par = 0;

    // --- prefetch step-0 gate seeds ---
    float4 xa, xb;       // layer 0: 8 x-values (broadcast)
    float  pseed = 0.f;  // layer 1: xp1 value for this gate row
    if (LAYER == 0) {
        const float4* xp = (const float4*)(xsrc + (size_t)b * TT * II);
        xa = xp[0]; xb = xp[1];
    } else {
        pseed = xsrc[(size_t)b * TT * GG + grow];
    }

    for (int s = 0; s < TT; s++) {
        float seed;
        const int sn = (s + 1 < TT) ? s + 1 : s;  // clamped prefetch index

        if (LAYER == 0) {
            seed = bsum;
            float xv[II];
            *(float4*)&xv[0] = xa; *(float4*)&xv[4] = xb;
#pragma unroll
            for (int k = 0; k < II; k++) seed = fmaf(wi[k], xv[k], seed);
            const float4* xp = (const float4*)(xsrc + ((size_t)b * TT + sn) * II);
            xa = xp[0]; xb = xp[1];
        } else {
            seed = pseed;
            pseed = xsrc[((size_t)b * TT + sn) * GG + grow];
        }

        // --- gate = w_row . h  (two f32x2 partial chains) ---
        ull acc2a = pack2(seed, 0.f);
        ull acc2b = 0ull;  // pack2(0,0)
        const ulonglong2* hq = (const ulonglong2*)hbuf[par];
#pragma unroll
        for (int k = 0; k < 16; k++) {
            ulonglong2 hp = hq[k];
            fma2(acc2a, wr[2 * k],     hp.x);
            fma2(acc2b, wr[2 * k + 1], hp.y);
        }
#pragma unroll
        for (int k = 16; k < 32; k++) {
            ulonglong2 hp = hq[k];
            fma2(acc2a, wr[2 * k],     hp.x);
            fma2(acc2b, wr[2 * k + 1], hp.y);
        }
        float acc = hsum2(acc2a) + hsum2(acc2b);

        // --- per-gate activation ---
        float a_i = 0.f;
        if (q == 0)      a_i = sigf(acc);
        else if (q == 1) fact[jl] = sigf(acc);
        else if (q == 2) gact[jl] = tanhf(acc);
        else             oact[jl] = sigf(acc);
        __syncthreads();

        const int nb = par ^ 1;
        if (q == 0) {
            c = fmaf(fact[jl], c, a_i * gact[jl]);
            float h = oact[jl] * tanhf(c);
            hbuf[nb][j] = h;
            sts_cluster_f32(peer_hbase + (unsigned)(nb * HH + j) * 4u, h);
            hout[((size_t)b * TT + s) * HH + j] = h;
        }
        __syncthreads();
        // Arrive AFTER the local barrier: guarantees every thread of this CTA
        // finished reading hbuf[par] before the peer (released by this arrive)
        // can advance far enough to overwrite it.
        if (q == 0) mbar_arrive_cluster(peer_mbar);
        mbar_wait_cluster(my_mbar, (unsigned)(s & 1));
        par = nb;
    }

    asm volatile("barrier.cluster.arrive.aligned;" ::: "memory");
    asm volatile("barrier.cluster.wait.aligned;"   ::: "memory");
}

// ---------------------------------------------------------------------------
// xp1[r][g] = sum_k h0[r][k] * w_ih1[g][k] + b_ih1[g] + b_hh1[g]
// M=192000, K=128, N=512.  128x128 tiles, 8x8 micro-tiles, k-fastest layout,
// inner product on the packed f32x2 pipe.
// ---------------------------------------------------------------------------
__global__ __launch_bounds__(256, 1) void gemm_xp1_kernel(
    const float* __restrict__ w_ih1,
    const float* __restrict__ b_ih1,
    const float* __restrict__ b_hh1)
{
    extern __shared__ float smem[];
    float4* As = (float4*)smem;       // [128][33]
    float4* Bs = As + 128 * 33;       // [128][33]

    const int tid = threadIdx.x;
    const int ty = tid >> 4;          // 0..15
    const int tx = tid & 15;          // 0..15
    const int rbase = blockIdx.x * 128;
    const int gbase = blockIdx.y * 128;

    const float4* h04 = (const float4*)g_h0;
    const float4* w4  = (const float4*)w_ih1;
    for (int i = tid; i < 128 * 32; i += 256) {
        int r = i >> 5, k4 = i & 31;
        As[r * 33 + k4] = h04[(size_t)(rbase + r) * 32 + k4];
    }
    for (int i = tid; i < 128 * 32; i += 256) {
        int g = i >> 5, k4 = i & 31;
        Bs[g * 33 + k4] = w4[(size_t)(gbase + g) * 32 + k4];
    }
    __syncthreads();

    ull acc2[8][8];
#pragma unroll
    for (int i = 0; i < 8; i++)
#pragma unroll
        for (int jj = 0; jj < 8; jj++) acc2[i][jj] = 0ull;

    const ulonglong2* As2 = (const ulonglong2*)As;
    const ulonglong2* Bs2 = (const ulonglong2*)Bs;
    for (int k4 = 0; k4 < 32; k4++) {
        ulonglong2 av[8], bv[8];
#pragma unroll
        for (int i = 0; i < 8; i++) av[i] = As2[(ty + 16 * i) * 33 + k4];
#pragma unroll
        for (int jj = 0; jj < 8; jj++) bv[jj] = Bs2[(tx + 16 * jj) * 33 + k4];
#pragma unroll
        for (int i = 0; i < 8; i++)
#pragma unroll
            for (int jj = 0; jj < 8; jj++) {
                fma2(acc2[i][jj], av[i].x, bv[jj].x);
                fma2(acc2[i][jj], av[i].y, bv[jj].y);
            }
    }

    float bb[8];
#pragma unroll
    for (int jj = 0; jj < 8; jj++) {
        int g = gbase + tx + 16 * jj;
        bb[jj] = b_ih1[g] + b_hh1[g];
    }
#pragma unroll
    for (int i = 0; i < 8; i++) {
        size_t row = (size_t)(rbase + ty + 16 * i);
#pragma unroll
        for (int jj = 0; jj < 8; jj++)
            g_xp1[row * GG + gbase + tx + 16 * jj] = hsum2(acc2[i][jj]) + bb[jj];
    }
}

// ---------------------------------------------------------------------------
// MLP head: y = fc3(relu(fc2(relu(fc1(h1))))). 64 positions / block.
// ---------------------------------------------------------------------------
__global__ __launch_bounds__(64) void mlp_kernel(
    const float* __restrict__ fc1w, const float* __restrict__ fc1b,
    const float* __restrict__ fc2w, const float* __restrict__ fc2b,
    const float* __restrict__ fc3w, const float* __restrict__ fc3b)
{
    __shared__ float hs[64 * 129];
    __shared__ float w1[16 * 128];
    __shared__ float b1s[16], w2s[64], b2s[4], w3s[4], b3s[1];

    const int tid = threadIdx.x;
    const size_t pos0 = (size_t)blockIdx.x * 64;

    const float4* h14 = (const float4*)g_h1;
    for (int i = tid; i < 64 * 32; i += 64) {
        int r = i >> 5, k4 = i & 31;
        float4 v = h14[(pos0 + r) * 32 + k4];
        float* d = &hs[r * 129 + k4 * 4];
        d[0] = v.x; d[1] = v.y; d[2] = v.z; d[3] = v.w;
    }
    for (int i = tid; i < 2048; i += 64) w1[i] = fc1w[i];
    if (tid < 16) b1s[tid] = fc1b[tid];
    if (tid < 64) w2s[tid] = fc2w[tid];
    if (tid < 4)  { b2s[tid] = fc2b[tid]; w3s[tid] = fc3w[tid]; }
    if (tid == 0) b3s[0] = fc3b[0];
    __syncthreads();

    float o1[16];
#pragma unroll
    for (int i = 0; i < 16; i++) o1[i] = b1s[i];
    const float* hp = &hs[tid * 129];
    for (int k = 0; k < 128; k++) {
        float hv = hp[k];
#pragma unroll
        for (int i = 0; i < 16; i++) o1[i] = fmaf(w1[i * 128 + k], hv, o1[i]);
    }
#pragma unroll
    for (int i = 0; i < 16; i++) o1[i] = fmaxf(o1[i], 0.f);

    float o2[4];
#pragma unroll
    for (int jj = 0; jj < 4; jj++) {
        float s = b2s[jj];
#pragma unroll
        for (int i = 0; i < 16; i++) s = fmaf(w2s[jj * 16 + i], o1[i], s);
        o2[jj] = fmaxf(s, 0.f);
    }
    float yv = b3s[0];
#pragma unroll
    for (int jj = 0; jj < 4; jj++) yv = fmaf(w3s[jj], o2[jj], yv);
    g_y[pos0 + tid] = yv;
}

// ---------------------------------------------------------------------------
// Double finite-difference: out = phi @ (phi @ y) per batch column.
// phi entries (pre-divided by dt=0.02) are exactly {±25, ±75, ±100} in fp32.
// ---------------------------------------------------------------------------
__global__ __launch_bounds__(256) void fd_kernel(float* __restrict__ out)
{
    __shared__ float ys[TT];
    __shared__ float d1[TT];
    const int b = blockIdx.x, tid = threadIdx.x;
    const float* yb = g_y + (size_t)b * TT;

    for (int t = tid; t < TT; t += 256) ys[t] = yb[t];
    __syncthreads();
    for (int t = tid; t < TT; t += 256) {
        float v;
        if (t == 0)           v = -75.f * ys[0] + 100.f * ys[1] - 25.f * ys[2];
        else if (t == TT - 1) v = 25.f * ys[TT-3] - 100.f * ys[TT-2] + 75.f * ys[TT-1];
        else                  v = 25.f * (ys[t + 1] - ys[t - 1]);
        d1[t] = v;
    }
    __syncthreads();
    for (int t = tid; t < TT; t += 256) {
        float v;
        if (t == 0)           v = -75.f * d1[0] + 100.f * d1[1] - 25.f * d1[2];
        else if (t == TT - 1) v = 25.f * d1[TT-3] - 100.f * d1[TT-2] + 75.f * d1[TT-1];
        else                  v = 25.f * (d1[t + 1] - d1[t - 1]);
        out[(size_t)b * TT + t] = v;
    }
}

// ---------------------------------------------------------------------------
// Launch
// ---------------------------------------------------------------------------
extern "C" void kernel_launch(void* const* d_in, const int* in_sizes, int n_in,
                              void* d_out, int out_size)
{
    const float* x     = (const float*)d_in[0];
    const float* w_ih0 = (const float*)d_in[1];
    const float* w_hh0 = (const float*)d_in[2];
    const float* b_ih0 = (const float*)d_in[3];
    const float* b_hh0 = (const float*)d_in[4];
    const float* w_ih1 = (const float*)d_in[5];
    const float* w_hh1 = (const float*)d_in[6];
    const float* b_ih1 = (const float*)d_in[7];
    const float* b_hh1 = (const float*)d_in[8];
    const float* fc1w  = (const float*)d_in[9];
    const float* fc1b  = (const float*)d_in[10];
    const float* fc2w  = (const float*)d_in[11];
    const float* fc2b  = (const float*)d_in[12];
    const float* fc3w  = (const float*)d_in[13];
    const float* fc3b  = (const float*)d_in[14];
    float* out = (float*)d_out;

    const int GEMM_SMEM = 2 * 128 * 33 * (int)sizeof(float4);  // 135168 B
    cudaFuncSetAttribute(gemm_xp1_kernel, cudaFuncAttributeMaxDynamicSharedMemorySize, GEMM_SMEM);

    // 1. Layer-0 LSTM (folds the I=8 input projection) -> g_h0
    lstm_kernel<0><<<BSZ * 2, 256>>>(x, w_ih0, w_hh0, b_ih0, b_hh0);
    // 2. Layer-1 input projection (+biases) -> g_xp1
    gemm_xp1_kernel<<<dim3((BSZ * TT) / 128, GG / 128), 256, GEMM_SMEM>>>(w_ih1, b_ih1, b_hh1);
    // 3. Layer-1 LSTM -> g_h1
    lstm_kernel<1><<<BSZ * 2, 256>>>(nullptr, nullptr, w_hh1, nullptr, nullptr);
    // 4. MLP head -> g_y
    mlp_kernel<<<(BSZ * TT) / 64, 64>>>(fc1w, fc1b, fc2w, fc2b, fc3w, fc3b);
    // 5. Double FD stencil -> out
    fd_kernel<<<BSZ, 256>>>(out);
}